// round 5
// baseline (speedup 1.0000x reference)
#include <cuda_runtime.h>
#include <cuda_bf16.h>

#define TB 256
#define BM 128
#define BN 128
#define BK 16

// Scratch for the two linear projections: [8, 2048, 256] f32 each.
__device__ __align__(16) float g_c1[8 * 2048 * 256];
__device__ __align__(16) float g_c2[8 * 2048 * 256];

// Elementwise epilogue (3 MUFU: EX2, RCP, EX2):
//   sig = sigmoid(s); c = 100*sig + 1e-5; cc = 1/(2 c^2); out = exp(-a^2 * cc)
__device__ __forceinline__ float epi(float s, float a) {
    float t = __expf(fminf(-s, 80.0f));               // MUFU ex2 (clamped: no inf)
    float u = 1.0f + t;
    float q = __fdividef(u, fmaf(1e-5f, u, 100.0f));  // MUFU rcp
    q *= 0.70710678f;
    float cc = q * q;                                  // = 1/(2 c^2)
    return __expf(-(a * a * cc));                      // MUFU ex2
}

// ---------------------------------------------------------------------------
// Shared inner machinery: 128x128 tile, 256 threads, 8x8 per thread, K=256.
// A rows = output rows, B rows = output cols, both row-major with K stride 256.
// ---------------------------------------------------------------------------
struct Frag { float acc[8][8]; };

__device__ __forceinline__ void gemm_tile_128x128(
    const float* __restrict__ A, const float* __restrict__ B,
    int r0, int c0, float (&acc)[8][8])
{
    const int K = 256;
    __shared__ __align__(16) float As[BK][BM + 4];
    __shared__ __align__(16) float Bs[BK][BN + 4];

    int tid = threadIdx.x;
    int tr = tid >> 4, tc = tid & 15;     // 16x16 thread grid
    int lr = tid >> 1, lc = (tid & 1) * 8;

#pragma unroll
    for (int i = 0; i < 8; i++)
#pragma unroll
        for (int j = 0; j < 8; j++) acc[i][j] = 0.0f;

    for (int k0 = 0; k0 < K; k0 += BK) {
        float4 a0 = *(const float4*)(A + (size_t)(r0 + lr) * K + k0 + lc);
        float4 a1 = *(const float4*)(A + (size_t)(r0 + lr) * K + k0 + lc + 4);
        float4 b0 = *(const float4*)(B + (size_t)(c0 + lr) * K + k0 + lc);
        float4 b1 = *(const float4*)(B + (size_t)(c0 + lr) * K + k0 + lc + 4);

        As[lc + 0][lr] = a0.x; As[lc + 1][lr] = a0.y;
        As[lc + 2][lr] = a0.z; As[lc + 3][lr] = a0.w;
        As[lc + 4][lr] = a1.x; As[lc + 5][lr] = a1.y;
        As[lc + 6][lr] = a1.z; As[lc + 7][lr] = a1.w;
        Bs[lc + 0][lr] = b0.x; Bs[lc + 1][lr] = b0.y;
        Bs[lc + 2][lr] = b0.z; Bs[lc + 3][lr] = b0.w;
        Bs[lc + 4][lr] = b1.x; Bs[lc + 5][lr] = b1.y;
        Bs[lc + 6][lr] = b1.z; Bs[lc + 7][lr] = b1.w;
        __syncthreads();

#pragma unroll
        for (int kk = 0; kk < BK; kk++) {
            float4 av0 = *(const float4*)&As[kk][tr * 8];
            float4 av1 = *(const float4*)&As[kk][tr * 8 + 4];
            float4 bv0 = *(const float4*)&Bs[kk][tc * 8];
            float4 bv1 = *(const float4*)&Bs[kk][tc * 8 + 4];
            float am[8] = {av0.x, av0.y, av0.z, av0.w, av1.x, av1.y, av1.z, av1.w};
            float bm[8] = {bv0.x, bv0.y, bv0.z, bv0.w, bv1.x, bv1.y, bv1.z, bv1.w};
#pragma unroll
            for (int i = 0; i < 8; i++)
#pragma unroll
                for (int j = 0; j < 8; j++)
                    acc[i][j] = fmaf(am[i], bm[j], acc[i][j]);
        }
        __syncthreads();
    }
}

// ---------------------------------------------------------------------------
// Projection: C = v(16384 x 256) * W(256 x 256)^T  -> g_c1 / g_c2
// ---------------------------------------------------------------------------
__global__ __launch_bounds__(TB) void proj_kernel(
    const float* __restrict__ v,
    const float* __restrict__ W1,
    const float* __restrict__ W2)
{
    const float* B = blockIdx.z ? W2 : W1;
    float* C = blockIdx.z ? g_c2 : g_c1;
    int m0 = blockIdx.x * BM;
    int n0 = blockIdx.y * BN;

    float acc[8][8];
    gemm_tile_128x128(v, B, m0, n0, acc);

    int tr = threadIdx.x >> 4, tc = threadIdx.x & 15;
#pragma unroll
    for (int i = 0; i < 8; i++) {
        size_t base = (size_t)(m0 + tr * 8 + i) * 256 + n0 + tc * 8;
        *(float4*)(C + base)     = make_float4(acc[i][0], acc[i][1], acc[i][2], acc[i][3]);
        *(float4*)(C + base + 4) = make_float4(acc[i][4], acc[i][5], acc[i][6], acc[i][7]);
    }
}

// ---------------------------------------------------------------------------
// Score GEMM + fused epilogue:
//   s[b,n,m] = sum_o c1[b,n,o] * c2[b,m,o];  out[b,n,m] = epi(s, adj[b,n,m])
// ---------------------------------------------------------------------------
__global__ __launch_bounds__(TB) void score_kernel(
    const float* __restrict__ adj,
    float* __restrict__ out)
{
    const int NN = 2048;
    int b = blockIdx.z;
    const float* A = g_c1 + (size_t)b * NN * 256;
    const float* B = g_c2 + (size_t)b * NN * 256;
    const float* adj_b = adj + (size_t)b * NN * NN;
    float* out_b = out + (size_t)b * NN * NN;

    int n0 = blockIdx.x * BM;
    int m0 = blockIdx.y * BN;

    float acc[8][8];
    gemm_tile_128x128(A, B, n0, m0, acc);

    int tr = threadIdx.x >> 4, tc = threadIdx.x & 15;
#pragma unroll
    for (int i = 0; i < 8; i++) {
        size_t base = (size_t)(n0 + tr * 8 + i) * NN + m0 + tc * 8;
        float4 a4 = *(const float4*)(adj_b + base);
        float4 b4 = *(const float4*)(adj_b + base + 4);
        float4 o0, o1;
        o0.x = epi(acc[i][0], a4.x);
        o0.y = epi(acc[i][1], a4.y);
        o0.z = epi(acc[i][2], a4.z);
        o0.w = epi(acc[i][3], a4.w);
        o1.x = epi(acc[i][4], b4.x);
        o1.y = epi(acc[i][5], b4.y);
        o1.z = epi(acc[i][6], b4.z);
        o1.w = epi(acc[i][7], b4.w);
        *(float4*)(out_b + base)     = o0;
        *(float4*)(out_b + base + 4) = o1;
    }
}

extern "C" void kernel_launch(void* const* d_in, const int* in_sizes, int n_in,
                              void* d_out, int out_size) {
    const float* v   = (const float*)d_in[0];
    const float* adj = (const float*)d_in[1];
    const float* W1  = (const float*)d_in[2];
    const float* W2  = (const float*)d_in[3];
    float* out = (float*)d_out;

    const long adj_elems = 8L * 2048 * 2048;      // 33,554,432
    long off = (long)out_size - adj_elems;        // leading v-passthrough elems
    if (off < 0) off = 0;

    if (off > 0) {
        // Output tuple element 0 is v unchanged.
        cudaMemcpyAsync(out, v, (size_t)off * sizeof(float),
                        cudaMemcpyDeviceToDevice, 0);
    }
    float* norm_adj = out + off;

    // Projections: c1 = v @ W1^T, c2 = v @ W2^T
    dim3 pgrid(16384 / BM, 256 / BN, 2);
    proj_kernel<<<pgrid, TB>>>(v, W1, W2);

    // Score GEMM + fused normalization epilogue
    dim3 sgrid(2048 / BM, 2048 / BN, 8);
    score_kernel<<<sgrid, TB>>>(adj, norm_adj);
}

// round 8
// speedup vs baseline: 1.8199x; 1.8199x over previous
#include <cuda_runtime.h>
#include <cuda_bf16.h>
#include <cstdint>

// ---------------- problem sizes ----------------
#define BATCH 8
#define NN    2048
#define KDIM  256
#define KCH   64      // K chunk staged in SMEM (bf16 elems, 128B rows)

// Projection outputs as bf16 hi/lo split: [8, 2048, 256] each.
__device__ __align__(16) __nv_bfloat16 g_c1hi[BATCH * NN * KDIM];
__device__ __align__(16) __nv_bfloat16 g_c1lo[BATCH * NN * KDIM];
__device__ __align__(16) __nv_bfloat16 g_c2hi[BATCH * NN * KDIM];
__device__ __align__(16) __nv_bfloat16 g_c2lo[BATCH * NN * KDIM];

// ---------------- helpers ----------------
__device__ __forceinline__ uint32_t smem_u32(const void* p) {
    uint32_t a;
    asm("{ .reg .u64 t; cvta.to.shared.u64 t, %1; cvt.u32.u64 %0, t; }"
        : "=r"(a) : "l"(p));
    return a;
}

// XOR swizzle for 128B rows: bits [4:6] ^= row%8 — conflict-free ldmatrix.
#define SW128(off) ((off) ^ (((off) >> 3) & 0x70))

__device__ __forceinline__ void ldsm_x4(uint32_t (&r)[4], uint32_t addr) {
    asm volatile("ldmatrix.sync.aligned.m8n8.x4.shared.b16 {%0,%1,%2,%3}, [%4];"
        : "=r"(r[0]), "=r"(r[1]), "=r"(r[2]), "=r"(r[3]) : "r"(addr));
}
__device__ __forceinline__ void ldsm_x2(uint32_t (&r)[2], uint32_t addr) {
    asm volatile("ldmatrix.sync.aligned.m8n8.x2.shared.b16 {%0,%1}, [%2];"
        : "=r"(r[0]), "=r"(r[1]) : "r"(addr));
}
__device__ __forceinline__ void mma_bf16(float (&d)[4], const uint32_t (&a)[4],
                                         const uint32_t b0, const uint32_t b1) {
    asm volatile(
        "mma.sync.aligned.m16n8k16.row.col.f32.bf16.bf16.f32 "
        "{%0,%1,%2,%3}, {%4,%5,%6,%7}, {%8,%9}, {%0,%1,%2,%3};"
        : "+f"(d[0]), "+f"(d[1]), "+f"(d[2]), "+f"(d[3])
        : "r"(a[0]), "r"(a[1]), "r"(a[2]), "r"(a[3]), "r"(b0), "r"(b1));
}
__device__ __forceinline__ void cp_async16(uint32_t dst, const void* src) {
    asm volatile("cp.async.cg.shared.global [%0], [%1], 16;" :: "r"(dst), "l"(src));
}
#define CP_COMMIT() asm volatile("cp.async.commit_group;" ::: "memory")
#define CP_WAIT1()  asm volatile("cp.async.wait_group 1;" ::: "memory")
#define CP_WAIT0()  asm volatile("cp.async.wait_group 0;" ::: "memory")

// ---------------- elementwise epilogue (3 MUFU) ----------------
__device__ __forceinline__ float epi(float s, float a) {
    float t = __expf(fminf(-s, 80.0f));
    float u = 1.0f + t;
    float q = __fdividef(u, fmaf(1e-5f, u, 100.0f));
    q *= 0.70710678f;
    float cc = q * q;                  // = 1/(2 c^2)
    return __expf(-(a * a * cc));
}

// ---------------------------------------------------------------------------
// Projection (SIMT fp32): C = v(16384x256) @ W(256x256)^T, emitted as bf16
// hi/lo split into g_c{1,2}{hi,lo}. Tile 128x64, 256 thr, 8x4 per thread.
// ---------------------------------------------------------------------------
__global__ __launch_bounds__(256) void proj_kernel(
    const float* __restrict__ v,
    const float* __restrict__ W1,
    const float* __restrict__ W2)
{
    const int K = 256;
    const float* B = blockIdx.z ? W2 : W1;
    __nv_bfloat16* Chi = blockIdx.z ? g_c2hi : g_c1hi;
    __nv_bfloat16* Clo = blockIdx.z ? g_c2lo : g_c1lo;

    __shared__ __align__(16) float As[16][132];
    __shared__ __align__(16) float Bs[16][68];

    int m0 = blockIdx.x * 128;
    int n0 = blockIdx.y * 64;
    int tid = threadIdx.x;
    int tr = tid >> 4, tc = tid & 15;
    int lrA = tid >> 1, lcA = (tid & 1) * 8;
    int lrB = tid >> 2, lcB = (tid & 3) * 4;

    float acc[8][4];
#pragma unroll
    for (int i = 0; i < 8; i++)
#pragma unroll
        for (int j = 0; j < 4; j++) acc[i][j] = 0.0f;

    for (int k0 = 0; k0 < K; k0 += 16) {
        float4 a0 = *(const float4*)(v + (size_t)(m0 + lrA) * K + k0 + lcA);
        float4 a1 = *(const float4*)(v + (size_t)(m0 + lrA) * K + k0 + lcA + 4);
        float4 b0 = *(const float4*)(B + (size_t)(n0 + lrB) * K + k0 + lcB);

        As[lcA + 0][lrA] = a0.x; As[lcA + 1][lrA] = a0.y;
        As[lcA + 2][lrA] = a0.z; As[lcA + 3][lrA] = a0.w;
        As[lcA + 4][lrA] = a1.x; As[lcA + 5][lrA] = a1.y;
        As[lcA + 6][lrA] = a1.z; As[lcA + 7][lrA] = a1.w;
        Bs[lcB + 0][lrB] = b0.x; Bs[lcB + 1][lrB] = b0.y;
        Bs[lcB + 2][lrB] = b0.z; Bs[lcB + 3][lrB] = b0.w;
        __syncthreads();

#pragma unroll
        for (int kk = 0; kk < 16; kk++) {
            float4 av0 = *(const float4*)&As[kk][tr * 8];
            float4 av1 = *(const float4*)&As[kk][tr * 8 + 4];
            float4 bv  = *(const float4*)&Bs[kk][tc * 4];
            float am[8] = {av0.x, av0.y, av0.z, av0.w, av1.x, av1.y, av1.z, av1.w};
            float bm[4] = {bv.x, bv.y, bv.z, bv.w};
#pragma unroll
            for (int i = 0; i < 8; i++)
#pragma unroll
                for (int j = 0; j < 4; j++)
                    acc[i][j] = fmaf(am[i], bm[j], acc[i][j]);
        }
        __syncthreads();
    }

#pragma unroll
    for (int i = 0; i < 8; i++) {
        size_t base = (size_t)(m0 + tr * 8 + i) * 256 + n0 + tc * 4;
        __nv_bfloat16 h[4], l[4];
#pragma unroll
        for (int j = 0; j < 4; j++) {
            float x = acc[i][j];
            h[j] = __float2bfloat16(x);
            l[j] = __float2bfloat16(x - __bfloat162float(h[j]));
        }
        *(__nv_bfloat162*)(Chi + base)     = __nv_bfloat162(h[0], h[1]);
        *(__nv_bfloat162*)(Chi + base + 2) = __nv_bfloat162(h[2], h[3]);
        *(__nv_bfloat162*)(Clo + base)     = __nv_bfloat162(l[0], l[1]);
        *(__nv_bfloat162*)(Clo + base + 2) = __nv_bfloat162(l[2], l[3]);
    }
}

// ---------------------------------------------------------------------------
// Score GEMM via mma.sync bf16 split (hh + hl + lh) + fused epilogue.
// CTA 128x128, 8 warps (2x4), warp tile 64x32 = 4x4 m16n8k16 tiles.
// Operands double-buffered in SMEM via cp.async, SW128-swizzled rows.
// ---------------------------------------------------------------------------
// SMEM: 2 bufs x 4 tiles (Ahi,Alo,Bhi,Blo) x 16KB (128 rows x 64 bf16).
#define SM_BUF(b, t) ((b) * 65536 + (t) * 16384)
#define SM_TOTAL     (2 * 65536)

__global__ __launch_bounds__(256, 1) void score_kernel(
    const float* __restrict__ adj,
    float* __restrict__ out)
{
    extern __shared__ __align__(1024) char smem[];
    uint32_t sm = smem_u32(smem);
    int tid = threadIdx.x;
    int wid = tid >> 5, lid = tid & 31;
    int b = blockIdx.z;
    int n0 = blockIdx.x * 128;     // output rows
    int m0 = blockIdx.y * 128;     // output cols

    const size_t boff = (size_t)b * NN * KDIM;
    const __nv_bfloat16* srcs[4] = {
        g_c1hi + boff + (size_t)n0 * KDIM,   // A hi (rows)
        g_c1lo + boff + (size_t)n0 * KDIM,   // A lo
        g_c2hi + boff + (size_t)m0 * KDIM,   // B hi (cols)
        g_c2lo + boff + (size_t)m0 * KDIM,   // B lo
    };

    // Fill one chunk (4 tiles of 128 rows x 64 bf16) into buffer `buf`.
    auto fill = [&](int buf, int ch) {
#pragma unroll
        for (int t = 0; t < 4; t++) {
            const __nv_bfloat16* s = srcs[t] + ch * KCH;
            uint32_t base = sm + SM_BUF(buf, t);
#pragma unroll
            for (int r = 0; r < 4; r++) {
                int idx = r * 256 + tid;       // 0..1023
                int row = idx >> 3;            // 0..127
                int col = (idx & 7) * 8;       // elems, 16B granules
                cp_async16(base + SW128((uint32_t)(row * 128 + col * 2)),
                           s + (size_t)row * KDIM + col);
            }
        }
        CP_COMMIT();
    };

    float acc[4][4][4];
#pragma unroll
    for (int mt = 0; mt < 4; mt++)
#pragma unroll
        for (int nt = 0; nt < 4; nt++)
#pragma unroll
            for (int r = 0; r < 4; r++) acc[mt][nt][r] = 0.0f;

    int wr = wid >> 2;       // 0..1 : row block of 64
    int wc = wid & 3;        // 0..3 : col block of 32

    // ldmatrix lane address components.
    int lt = lid >> 3;       // 0..3 (tile group)
    int lr = lid & 7;        // row within 8

    fill(0, 0);

    for (int ch = 0; ch < 4; ch++) {
        int buf = ch & 1;
        if (ch < 3) fill(buf ^ 1, ch + 1);
        if (ch < 3) CP_WAIT1(); else CP_WAIT0();
        __syncthreads();

        uint32_t aHi = sm + SM_BUF(buf, 0);
        uint32_t aLo = sm + SM_BUF(buf, 1);
        uint32_t bHi = sm + SM_BUF(buf, 2);
        uint32_t bLo = sm + SM_BUF(buf, 3);

#pragma unroll
        for (int ks = 0; ks < 4; ks++) {
            int k0 = ks * 16;
            // A fragments: 4 m-tiles, hi+lo. x4 lane addr:
            //   row = wr*64 + mt*16 + (lt&1)*8 + lr, kbyte = (k0 + (lt>>1)*8)*2
            uint32_t Ah[4][4], Al[4][4];
#pragma unroll
            for (int mt = 0; mt < 4; mt++) {
                uint32_t off = SW128((uint32_t)(
                    (wr * 64 + mt * 16 + (lt & 1) * 8 + lr) * 128 +
                    (k0 + (lt >> 1) * 8) * 2));
                ldsm_x4(Ah[mt], aHi + off);
                ldsm_x4(Al[mt], aLo + off);
            }
            // B fragments: 4 n-tiles, hi+lo. x2 lane addr (lanes 0-15):
            //   row = wc*32 + nt*8 + lr, kbyte = (k0 + (lt&1)*8)*2
            uint32_t Bh[4][2], Bl[4][2];
#pragma unroll
            for (int nt = 0; nt < 4; nt++) {
                uint32_t off = SW128((uint32_t)(
                    (wc * 32 + nt * 8 + lr) * 128 + (k0 + (lt & 1) * 8) * 2));
                ldsm_x2(Bh[nt], bHi + off);
                ldsm_x2(Bl[nt], bLo + off);
            }
#pragma unroll
            for (int mt = 0; mt < 4; mt++)
#pragma unroll
                for (int nt = 0; nt < 4; nt++) {
                    mma_bf16(acc[mt][nt], Ah[mt], Bh[nt][0], Bh[nt][1]);
                    mma_bf16(acc[mt][nt], Ah[mt], Bl[nt][0], Bl[nt][1]);
                    mma_bf16(acc[mt][nt], Al[mt], Bh[nt][0], Bh[nt][1]);
                }
        }
        __syncthreads();
    }

    // Fused epilogue straight from accumulators.
    // d-frag: rows (lid>>2)+{0,8}, cols (lid&3)*2+{0,1}.
    const float* adj_b = adj + ((size_t)b * NN + n0) * NN + m0;
    float* out_b = out + ((size_t)b * NN + n0) * NN + m0;
    int Rb = wr * 64 + (lid >> 2);
    int Cb = wc * 32 + (lid & 3) * 2;
#pragma unroll
    for (int mt = 0; mt < 4; mt++) {
#pragma unroll
        for (int h = 0; h < 2; h++) {
            size_t row = (size_t)(Rb + mt * 16 + h * 8) * NN;
#pragma unroll
            for (int nt = 0; nt < 4; nt++) {
                size_t o = row + Cb + nt * 8;
                float2 a2 = *(const float2*)(adj_b + o);
                float2 r;
                r.x = epi(acc[mt][nt][h * 2 + 0], a2.x);
                r.y = epi(acc[mt][nt][h * 2 + 1], a2.y);
                *(float2*)(out_b + o) = r;
            }
        }
    }
}

extern "C" void kernel_launch(void* const* d_in, const int* in_sizes, int n_in,
                              void* d_out, int out_size) {
    const float* v   = (const float*)d_in[0];
    const float* adj = (const float*)d_in[1];
    const float* W1  = (const float*)d_in[2];
    const float* W2  = (const float*)d_in[3];
    float* out = (float*)d_out;

    const long adj_elems = 8L * 2048 * 2048;
    long off = (long)out_size - adj_elems;
    if (off < 0) off = 0;
    if (off > 0) {
        cudaMemcpyAsync(out, v, (size_t)off * sizeof(float),
                        cudaMemcpyDeviceToDevice, 0);
    }
    float* norm_adj = out + off;

    // Projections -> bf16 hi/lo scratch
    dim3 pgrid(16384 / 128, 256 / 64, 2);
    proj_kernel<<<pgrid, 256>>>(v, W1, W2);

    // mma.sync score GEMM + fused epilogue
    cudaFuncSetAttribute(score_kernel,
                         cudaFuncAttributeMaxDynamicSharedMemorySize, SM_TOTAL);
    dim3 sgrid(NN / 128, NN / 128, BATCH);
    score_kernel<<<sgrid, 256, SM_TOTAL>>>(adj, norm_adj);
}

// round 9
// speedup vs baseline: 2.6870x; 1.4765x over previous
#include <cuda_runtime.h>
#include <cuda_bf16.h>
#include <cstdint>

// ---------------- problem sizes ----------------
#define BATCH 8
#define NN    2048
#define KDIM  256
#define KCH   64      // K chunk staged in SMEM (bf16 elems, 128B rows)
#define NV    (BATCH * NN * KDIM)   // 4,194,304 v elems
#define NW    (256 * 256)           // W elems

// bf16 hi/lo splits of inputs and projections.
__device__ __align__(16) __nv_bfloat16 g_vhi[NV],  g_vlo[NV];
__device__ __align__(16) __nv_bfloat16 g_w1hi[NW], g_w1lo[NW];
__device__ __align__(16) __nv_bfloat16 g_w2hi[NW], g_w2lo[NW];
__device__ __align__(16) __nv_bfloat16 g_c1hi[NV], g_c1lo[NV];
__device__ __align__(16) __nv_bfloat16 g_c2hi[NV], g_c2lo[NV];

// ---------------- helpers ----------------
__device__ __forceinline__ uint32_t smem_u32(const void* p) {
    uint32_t a;
    asm("{ .reg .u64 t; cvta.to.shared.u64 t, %1; cvt.u32.u64 %0, t; }"
        : "=r"(a) : "l"(p));
    return a;
}

#define SW128(off) ((off) ^ (((off) >> 3) & 0x70))

__device__ __forceinline__ void ldsm_x4(uint32_t (&r)[4], uint32_t addr) {
    asm volatile("ldmatrix.sync.aligned.m8n8.x4.shared.b16 {%0,%1,%2,%3}, [%4];"
        : "=r"(r[0]), "=r"(r[1]), "=r"(r[2]), "=r"(r[3]) : "r"(addr));
}
__device__ __forceinline__ void ldsm_x2(uint32_t (&r)[2], uint32_t addr) {
    asm volatile("ldmatrix.sync.aligned.m8n8.x2.shared.b16 {%0,%1}, [%2];"
        : "=r"(r[0]), "=r"(r[1]) : "r"(addr));
}
__device__ __forceinline__ void mma_bf16(float (&d)[4], const uint32_t (&a)[4],
                                         const uint32_t b0, const uint32_t b1) {
    asm volatile(
        "mma.sync.aligned.m16n8k16.row.col.f32.bf16.bf16.f32 "
        "{%0,%1,%2,%3}, {%4,%5,%6,%7}, {%8,%9}, {%0,%1,%2,%3};"
        : "+f"(d[0]), "+f"(d[1]), "+f"(d[2]), "+f"(d[3])
        : "r"(a[0]), "r"(a[1]), "r"(a[2]), "r"(a[3]), "r"(b0), "r"(b1));
}
__device__ __forceinline__ void cp_async16(uint32_t dst, const void* src) {
    asm volatile("cp.async.cg.shared.global [%0], [%1], 16;" :: "r"(dst), "l"(src));
}
#define CP_COMMIT() asm volatile("cp.async.commit_group;" ::: "memory")
#define CP_WAIT1()  asm volatile("cp.async.wait_group 1;" ::: "memory")
#define CP_WAIT0()  asm volatile("cp.async.wait_group 0;" ::: "memory")

// ---------------- elementwise epilogue (3 MUFU) ----------------
__device__ __forceinline__ float epi(float s, float a) {
    float t = __expf(fminf(-s, 80.0f));
    float u = 1.0f + t;
    float q = __fdividef(u, fmaf(1e-5f, u, 100.0f));
    q *= 0.70710678f;
    float cc = q * q;                  // = 1/(2 c^2)
    return __expf(-(a * a * cc));
}

__device__ __forceinline__ void split_store(__nv_bfloat16* hi, __nv_bfloat16* lo,
                                            int t, float4 x) {
    float xs[4] = {x.x, x.y, x.z, x.w};
    __nv_bfloat16 h[4], l[4];
#pragma unroll
    for (int j = 0; j < 4; j++) {
        h[j] = __float2bfloat16(xs[j]);
        l[j] = __float2bfloat16(xs[j] - __bfloat162float(h[j]));
    }
    *(__nv_bfloat162*)(hi + 4 * t)     = __nv_bfloat162(h[0], h[1]);
    *(__nv_bfloat162*)(hi + 4 * t + 2) = __nv_bfloat162(h[2], h[3]);
    *(__nv_bfloat162*)(lo + 4 * t)     = __nv_bfloat162(l[0], l[1]);
    *(__nv_bfloat162*)(lo + 4 * t + 2) = __nv_bfloat162(l[2], l[3]);
}

// ---------------------------------------------------------------------------
// Split kernel: v -> (g_vhi, g_vlo) + v passthrough copy; W1/W2 -> splits.
// ---------------------------------------------------------------------------
__global__ __launch_bounds__(256) void split_kernel(
    const float* __restrict__ v,
    const float* __restrict__ W1,
    const float* __restrict__ W2,
    float* __restrict__ out_v)
{
    const int NV4 = NV / 4, NW4 = NW / 4;
    int t = blockIdx.x * 256 + threadIdx.x;
    if (t < NV4) {
        float4 x = ((const float4*)v)[t];
        if (out_v) ((float4*)out_v)[t] = x;
        split_store(g_vhi, g_vlo, t, x);
    } else if (t < NV4 + NW4) {
        int i = t - NV4;
        split_store(g_w1hi, g_w1lo, i, ((const float4*)W1)[i]);
    } else if (t < NV4 + 2 * NW4) {
        int i = t - NV4 - NW4;
        split_store(g_w2hi, g_w2lo, i, ((const float4*)W2)[i]);
    }
}

// ---------------------------------------------------------------------------
// Projection via mma.sync (3-term bf16): c = v @ W^T, K=256.
// CTA 128 rows x 64 cols, 8 warps (2x4), warp tile 64x16 (4x2 m16n8k16).
// Double-buffered cp.async operands. Epilogue splits c -> bf16 hi/lo.
// SMEM per buf: Ahi 16K | Alo 16K | Bhi 8K | Blo 8K = 48KB; x2 = 96KB.
// ---------------------------------------------------------------------------
#define PSM_BUF(b) ((b) * 49152)
#define PSM_A_HI(b) (PSM_BUF(b) + 0)
#define PSM_A_LO(b) (PSM_BUF(b) + 16384)
#define PSM_B_HI(b) (PSM_BUF(b) + 32768)
#define PSM_B_LO(b) (PSM_BUF(b) + 40960)
#define PSM_TOTAL   (2 * 49152)

__global__ __launch_bounds__(256) void proj_kernel()
{
    extern __shared__ __align__(1024) char smem[];
    uint32_t sm = smem_u32(smem);
    int tid = threadIdx.x;
    int wid = tid >> 5, lid = tid & 31;
    int row0 = blockIdx.x * 128;          // v rows
    int n0 = blockIdx.y * 64;             // output features
    int which = blockIdx.z;

    const __nv_bfloat16* Ahi = g_vhi + (size_t)row0 * KDIM;
    const __nv_bfloat16* Alo = g_vlo + (size_t)row0 * KDIM;
    const __nv_bfloat16* Bhi = (which ? g_w2hi : g_w1hi) + (size_t)n0 * KDIM;
    const __nv_bfloat16* Blo = (which ? g_w2lo : g_w1lo) + (size_t)n0 * KDIM;
    __nv_bfloat16* Chi = which ? g_c2hi : g_c1hi;
    __nv_bfloat16* Clo = which ? g_c2lo : g_c1lo;

    auto fill = [&](int buf, int ch) {
        int k0 = ch * KCH;
        // A tiles: 128 rows x 64 bf16 each (hi, lo) -> 4 x 16B per thread each.
#pragma unroll
        for (int r = 0; r < 4; r++) {
            int idx = r * 256 + tid;          // 0..1023
            int row = idx >> 3, col = (idx & 7) * 8;
            uint32_t off = SW128((uint32_t)(row * 128 + col * 2));
            cp_async16(sm + PSM_A_HI(buf) + off, Ahi + (size_t)row * KDIM + k0 + col);
            cp_async16(sm + PSM_A_LO(buf) + off, Alo + (size_t)row * KDIM + k0 + col);
        }
        // B tiles: 64 rows x 64 bf16 each -> 2 x 16B per thread each.
#pragma unroll
        for (int r = 0; r < 2; r++) {
            int idx = r * 256 + tid;          // 0..511
            int row = idx >> 3, col = (idx & 7) * 8;
            uint32_t off = SW128((uint32_t)(row * 128 + col * 2));
            cp_async16(sm + PSM_B_HI(buf) + off, Bhi + (size_t)row * KDIM + k0 + col);
            cp_async16(sm + PSM_B_LO(buf) + off, Blo + (size_t)row * KDIM + k0 + col);
        }
        CP_COMMIT();
    };

    float acc[4][2][4];
#pragma unroll
    for (int mt = 0; mt < 4; mt++)
#pragma unroll
        for (int nt = 0; nt < 2; nt++)
#pragma unroll
            for (int r = 0; r < 4; r++) acc[mt][nt][r] = 0.0f;

    int wr = wid >> 2;      // 0..1 : 64-row block
    int wc = wid & 3;       // 0..3 : 16-col block
    int lt = lid >> 3, lr = lid & 7;

    fill(0, 0);
    for (int ch = 0; ch < 4; ch++) {
        int buf = ch & 1;
        if (ch < 3) fill(buf ^ 1, ch + 1);
        if (ch < 3) CP_WAIT1(); else CP_WAIT0();
        __syncthreads();

#pragma unroll
        for (int ks = 0; ks < 4; ks++) {
            int k0 = ks * 16;
            uint32_t Ah[4][4], Al[4][4];
#pragma unroll
            for (int mt = 0; mt < 4; mt++) {
                uint32_t off = SW128((uint32_t)(
                    (wr * 64 + mt * 16 + (lt & 1) * 8 + lr) * 128 +
                    (k0 + (lt >> 1) * 8) * 2));
                ldsm_x4(Ah[mt], sm + PSM_A_HI(buf) + off);
                ldsm_x4(Al[mt], sm + PSM_A_LO(buf) + off);
            }
            uint32_t Bh[2][2], Bl[2][2];
#pragma unroll
            for (int nt = 0; nt < 2; nt++) {
                uint32_t off = SW128((uint32_t)(
                    (wc * 16 + nt * 8 + lr) * 128 + (k0 + (lt & 1) * 8) * 2));
                ldsm_x2(Bh[nt], sm + PSM_B_HI(buf) + off);
                ldsm_x2(Bl[nt], sm + PSM_B_LO(buf) + off);
            }
#pragma unroll
            for (int mt = 0; mt < 4; mt++)
#pragma unroll
                for (int nt = 0; nt < 2; nt++) {
                    mma_bf16(acc[mt][nt], Ah[mt], Bh[nt][0], Bh[nt][1]);
                    mma_bf16(acc[mt][nt], Ah[mt], Bl[nt][0], Bl[nt][1]);
                    mma_bf16(acc[mt][nt], Al[mt], Bh[nt][0], Bh[nt][1]);
                }
        }
        __syncthreads();
    }

    // Epilogue: split c into bf16 hi/lo and store.
    int Rb = wr * 64 + (lid >> 2);
    int Cb = wc * 16 + (lid & 3) * 2;
#pragma unroll
    for (int mt = 0; mt < 4; mt++)
#pragma unroll
        for (int h = 0; h < 2; h++) {
            size_t row = (size_t)(row0 + Rb + mt * 16 + h * 8) * KDIM;
#pragma unroll
            for (int nt = 0; nt < 2; nt++) {
                size_t o = row + n0 + Cb + nt * 8;
                float c0 = acc[mt][nt][h * 2 + 0];
                float c1 = acc[mt][nt][h * 2 + 1];
                __nv_bfloat16 h0 = __float2bfloat16(c0);
                __nv_bfloat16 h1 = __float2bfloat16(c1);
                __nv_bfloat16 l0 = __float2bfloat16(c0 - __bfloat162float(h0));
                __nv_bfloat16 l1 = __float2bfloat16(c1 - __bfloat162float(h1));
                *(__nv_bfloat162*)(Chi + o) = __nv_bfloat162(h0, h1);
                *(__nv_bfloat162*)(Clo + o) = __nv_bfloat162(l0, l1);
            }
        }
}

// ---------------------------------------------------------------------------
// Score GEMM (3-term bf16 mma.sync) + fused epilogue.
// CTA 64(n) x 128(m), 128 threads (4 warps), warp tile 64x32. 2 CTAs/SM.
// SMEM per buf: Ahi 8K | Alo 8K | Bhi 16K | Blo 16K = 48KB; x2 = 96KB.
// ---------------------------------------------------------------------------
#define SSM_BUF(b) ((b) * 49152)
#define SSM_A_HI(b) (SSM_BUF(b) + 0)
#define SSM_A_LO(b) (SSM_BUF(b) + 8192)
#define SSM_B_HI(b) (SSM_BUF(b) + 16384)
#define SSM_B_LO(b) (SSM_BUF(b) + 32768)
#define SSM_TOTAL   (2 * 49152)

__global__ __launch_bounds__(128) void score_kernel(
    const float* __restrict__ adj,
    float* __restrict__ out)
{
    extern __shared__ __align__(1024) char smem[];
    uint32_t sm = smem_u32(smem);
    int tid = threadIdx.x;
    int wid = tid >> 5, lid = tid & 31;
    int b = blockIdx.z;
    int n0 = blockIdx.x * 64;      // output rows
    int m0 = blockIdx.y * 128;     // output cols

    const size_t boff = (size_t)b * NN * KDIM;
    const __nv_bfloat16* Ahi = g_c1hi + boff + (size_t)n0 * KDIM;
    const __nv_bfloat16* Alo = g_c1lo + boff + (size_t)n0 * KDIM;
    const __nv_bfloat16* Bhi = g_c2hi + boff + (size_t)m0 * KDIM;
    const __nv_bfloat16* Blo = g_c2lo + boff + (size_t)m0 * KDIM;

    auto fill = [&](int buf, int ch) {
        int k0 = ch * KCH;
        // A tiles: 64 rows x 64 bf16 -> 4 x 16B per thread each (hi, lo).
#pragma unroll
        for (int r = 0; r < 4; r++) {
            int idx = r * 128 + tid;          // 0..511
            int row = idx >> 3, col = (idx & 7) * 8;
            uint32_t off = SW128((uint32_t)(row * 128 + col * 2));
            cp_async16(sm + SSM_A_HI(buf) + off, Ahi + (size_t)row * KDIM + k0 + col);
            cp_async16(sm + SSM_A_LO(buf) + off, Alo + (size_t)row * KDIM + k0 + col);
        }
        // B tiles: 128 rows x 64 bf16 -> 8 x 16B per thread each.
#pragma unroll
        for (int r = 0; r < 8; r++) {
            int idx = r * 128 + tid;          // 0..1023
            int row = idx >> 3, col = (idx & 7) * 8;
            uint32_t off = SW128((uint32_t)(row * 128 + col * 2));
            cp_async16(sm + SSM_B_HI(buf) + off, Bhi + (size_t)row * KDIM + k0 + col);
            cp_async16(sm + SSM_B_LO(buf) + off, Blo + (size_t)row * KDIM + k0 + col);
        }
        CP_COMMIT();
    };

    float acc[4][4][4];
#pragma unroll
    for (int mt = 0; mt < 4; mt++)
#pragma unroll
        for (int nt = 0; nt < 4; nt++)
#pragma unroll
            for (int r = 0; r < 4; r++) acc[mt][nt][r] = 0.0f;

    int wc = wid;           // 0..3 : 32-col block
    int lt = lid >> 3, lr = lid & 7;

    fill(0, 0);
    for (int ch = 0; ch < 4; ch++) {
        int buf = ch & 1;
        if (ch < 3) fill(buf ^ 1, ch + 1);
        if (ch < 3) CP_WAIT1(); else CP_WAIT0();
        __syncthreads();

#pragma unroll
        for (int ks = 0; ks < 4; ks++) {
            int k0 = ks * 16;
            uint32_t Ah[4][4], Al[4][4];
#pragma unroll
            for (int mt = 0; mt < 4; mt++) {
                uint32_t off = SW128((uint32_t)(
                    (mt * 16 + (lt & 1) * 8 + lr) * 128 +
                    (k0 + (lt >> 1) * 8) * 2));
                ldsm_x4(Ah[mt], sm + SSM_A_HI(buf) + off);
                ldsm_x4(Al[mt], sm + SSM_A_LO(buf) + off);
            }
            uint32_t Bh[4][2], Bl[4][2];
#pragma unroll
            for (int nt = 0; nt < 4; nt++) {
                uint32_t off = SW128((uint32_t)(
                    (wc * 32 + nt * 8 + lr) * 128 + (k0 + (lt & 1) * 8) * 2));
                ldsm_x2(Bh[nt], sm + SSM_B_HI(buf) + off);
                ldsm_x2(Bl[nt], sm + SSM_B_LO(buf) + off);
            }
#pragma unroll
            for (int mt = 0; mt < 4; mt++)
#pragma unroll
                for (int nt = 0; nt < 4; nt++) {
                    mma_bf16(acc[mt][nt], Ah[mt], Bh[nt][0], Bh[nt][1]);
                    mma_bf16(acc[mt][nt], Ah[mt], Bl[nt][0], Bl[nt][1]);
                    mma_bf16(acc[mt][nt], Al[mt], Bh[nt][0], Bh[nt][1]);
                }
        }
        __syncthreads();
    }

    // Fused epilogue straight from accumulators.
    const float* adj_b = adj + ((size_t)b * NN + n0) * NN + m0;
    float* out_b = out + ((size_t)b * NN + n0) * NN + m0;
    int Rb = lid >> 2;
    int Cb = wc * 32 + (lid & 3) * 2;
#pragma unroll
    for (int mt = 0; mt < 4; mt++) {
#pragma unroll
        for (int h = 0; h < 2; h++) {
            size_t row = (size_t)(Rb + mt * 16 + h * 8) * NN;
#pragma unroll
            for (int nt = 0; nt < 4; nt++) {
                size_t o = row + Cb + nt * 8;
                float2 a2 = *(const float2*)(adj_b + o);
                float2 r;
                r.x = epi(acc[mt][nt][h * 2 + 0], a2.x);
                r.y = epi(acc[mt][nt][h * 2 + 1], a2.y);
                *(float2*)(out_b + o) = r;
            }
        }
    }
}

extern "C" void kernel_launch(void* const* d_in, const int* in_sizes, int n_in,
                              void* d_out, int out_size) {
    const float* v   = (const float*)d_in[0];
    const float* adj = (const float*)d_in[1];
    const float* W1  = (const float*)d_in[2];
    const float* W2  = (const float*)d_in[3];
    float* out = (float*)d_out;

    const long adj_elems = 8L * 2048 * 2048;
    long off = (long)out_size - adj_elems;
    if (off < 0) off = 0;
    float* norm_adj = out + off;
    float* out_v = (off > 0) ? out : nullptr;

    // 1. Split v/W into bf16 hi/lo (+ v passthrough copy).
    int split_ctas = (NV / 4 + 2 * (NW / 4) + 255) / 256;
    split_kernel<<<split_ctas, 256>>>(v, W1, W2, out_v);

    // 2. Projections via mma.sync -> g_c{1,2}{hi,lo}.
    cudaFuncSetAttribute(proj_kernel,
                         cudaFuncAttributeMaxDynamicSharedMemorySize, PSM_TOTAL);
    dim3 pgrid(16384 / 128, 256 / 64, 2);
    proj_kernel<<<pgrid, 256, PSM_TOTAL>>>();

    // 3. Score GEMM + fused epilogue (2 CTAs/SM).
    cudaFuncSetAttribute(score_kernel,
                         cudaFuncAttributeMaxDynamicSharedMemorySize, SSM_TOTAL);
    dim3 sgrid(NN / 64, NN / 128, BATCH);
    score_kernel<<<sgrid, 128, SSM_TOTAL>>>(adj, norm_adj);
}

// round 10
// speedup vs baseline: 2.8028x; 1.0431x over previous
#include <cuda_runtime.h>
#include <cuda_bf16.h>
#include <cstdint>

// ---------------- problem sizes ----------------
#define BATCH 8
#define NN    2048
#define KDIM  256
#define NV    (BATCH * NN * KDIM)   // 4,194,304 v elems
#define NW    (256 * 256)           // W elems

// bf16 hi/lo splits of inputs and projections.
__device__ __align__(16) __nv_bfloat16 g_vhi[NV],  g_vlo[NV];
__device__ __align__(16) __nv_bfloat16 g_w1hi[NW], g_w1lo[NW];
__device__ __align__(16) __nv_bfloat16 g_w2hi[NW], g_w2lo[NW];
__device__ __align__(16) __nv_bfloat16 g_c1hi[NV], g_c1lo[NV];
__device__ __align__(16) __nv_bfloat16 g_c2hi[NV], g_c2lo[NV];

// ---------------- helpers ----------------
__device__ __forceinline__ uint32_t smem_u32(const void* p) {
    uint32_t a;
    asm("{ .reg .u64 t; cvta.to.shared.u64 t, %1; cvt.u32.u64 %0, t; }"
        : "=r"(a) : "l"(p));
    return a;
}

#define SW128(off) ((off) ^ (((off) >> 3) & 0x70))   // 128B-row swizzle
#define SW64(off)  ((off) ^ (((off) >> 3) & 0x30))   // 64B-row swizzle

__device__ __forceinline__ void ldsm_x4(uint32_t (&r)[4], uint32_t addr) {
    asm volatile("ldmatrix.sync.aligned.m8n8.x4.shared.b16 {%0,%1,%2,%3}, [%4];"
        : "=r"(r[0]), "=r"(r[1]), "=r"(r[2]), "=r"(r[3]) : "r"(addr));
}
__device__ __forceinline__ void ldsm_x2(uint32_t (&r)[2], uint32_t addr) {
    asm volatile("ldmatrix.sync.aligned.m8n8.x2.shared.b16 {%0,%1}, [%2];"
        : "=r"(r[0]), "=r"(r[1]) : "r"(addr));
}
__device__ __forceinline__ void mma_bf16(float (&d)[4], const uint32_t (&a)[4],
                                         const uint32_t b0, const uint32_t b1) {
    asm volatile(
        "mma.sync.aligned.m16n8k16.row.col.f32.bf16.bf16.f32 "
        "{%0,%1,%2,%3}, {%4,%5,%6,%7}, {%8,%9}, {%0,%1,%2,%3};"
        : "+f"(d[0]), "+f"(d[1]), "+f"(d[2]), "+f"(d[3])
        : "r"(a[0]), "r"(a[1]), "r"(a[2]), "r"(a[3]), "r"(b0), "r"(b1));
}
__device__ __forceinline__ void cp_async16(uint32_t dst, const void* src) {
    asm volatile("cp.async.cg.shared.global [%0], [%1], 16;" :: "r"(dst), "l"(src));
}
#define CP_COMMIT() asm volatile("cp.async.commit_group;" ::: "memory")
#define CP_WAIT1()  asm volatile("cp.async.wait_group 1;" ::: "memory")
#define CP_WAIT0()  asm volatile("cp.async.wait_group 0;" ::: "memory")

// ---------------- elementwise epilogue (3 MUFU) ----------------
__device__ __forceinline__ float epi(float s, float a) {
    float t = __expf(fminf(-s, 80.0f));
    float u = 1.0f + t;
    float q = __fdividef(u, fmaf(1e-5f, u, 100.0f));
    q *= 0.70710678f;
    float cc = q * q;                  // = 1/(2 c^2)
    return __expf(-(a * a * cc));
}

__device__ __forceinline__ void split_store(__nv_bfloat16* hi, __nv_bfloat16* lo,
                                            int t, float4 x) {
    float xs[4] = {x.x, x.y, x.z, x.w};
    __nv_bfloat16 h[4], l[4];
#pragma unroll
    for (int j = 0; j < 4; j++) {
        h[j] = __float2bfloat16(xs[j]);
        l[j] = __float2bfloat16(xs[j] - __bfloat162float(h[j]));
    }
    *(__nv_bfloat162*)(hi + 4 * t)     = __nv_bfloat162(h[0], h[1]);
    *(__nv_bfloat162*)(hi + 4 * t + 2) = __nv_bfloat162(h[2], h[3]);
    *(__nv_bfloat162*)(lo + 4 * t)     = __nv_bfloat162(l[0], l[1]);
    *(__nv_bfloat162*)(lo + 4 * t + 2) = __nv_bfloat162(l[2], l[3]);
}

// ---------------------------------------------------------------------------
// Split kernel: v -> (g_vhi, g_vlo) + v passthrough copy; W1/W2 -> splits.
// ---------------------------------------------------------------------------
__global__ __launch_bounds__(256) void split_kernel(
    const float* __restrict__ v,
    const float* __restrict__ W1,
    const float* __restrict__ W2,
    float* __restrict__ out_v)
{
    const int NV4 = NV / 4, NW4 = NW / 4;
    int t = blockIdx.x * 256 + threadIdx.x;
    if (t < NV4) {
        float4 x = ((const float4*)v)[t];
        if (out_v) ((float4*)out_v)[t] = x;
        split_store(g_vhi, g_vlo, t, x);
    } else if (t < NV4 + NW4) {
        int i = t - NV4;
        split_store(g_w1hi, g_w1lo, i, ((const float4*)W1)[i]);
    } else if (t < NV4 + 2 * NW4) {
        int i = t - NV4 - NW4;
        split_store(g_w2hi, g_w2lo, i, ((const float4*)W2)[i]);
    }
}

// ---------------------------------------------------------------------------
// Projection via mma.sync (3-term bf16): c = v @ W^T, K=256.
// CTA 128 rows x 64 cols, 8 warps (2x4), warp tile 64x16 (4x2 m16n8k16).
// KCH=64, SW128 rows. 2 CTAs/SM (96KB SMEM, regs<=128).
// ---------------------------------------------------------------------------
#define PKCH 64
#define PSM_BUF(b) ((b) * 49152)
#define PSM_A_HI(b) (PSM_BUF(b) + 0)
#define PSM_A_LO(b) (PSM_BUF(b) + 16384)
#define PSM_B_HI(b) (PSM_BUF(b) + 32768)
#define PSM_B_LO(b) (PSM_BUF(b) + 40960)
#define PSM_TOTAL   (2 * 49152)

__global__ __launch_bounds__(256, 2) void proj_kernel()
{
    extern __shared__ __align__(1024) char smem[];
    uint32_t sm = smem_u32(smem);
    int tid = threadIdx.x;
    int wid = tid >> 5, lid = tid & 31;
    int row0 = blockIdx.x * 128;          // v rows
    int n0 = blockIdx.y * 64;             // output features
    int which = blockIdx.z;

    const __nv_bfloat16* Ahi = g_vhi + (size_t)row0 * KDIM;
    const __nv_bfloat16* Alo = g_vlo + (size_t)row0 * KDIM;
    const __nv_bfloat16* Bhi = (which ? g_w2hi : g_w1hi) + (size_t)n0 * KDIM;
    const __nv_bfloat16* Blo = (which ? g_w2lo : g_w1lo) + (size_t)n0 * KDIM;
    __nv_bfloat16* Chi = which ? g_c2hi : g_c1hi;
    __nv_bfloat16* Clo = which ? g_c2lo : g_c1lo;

    auto fill = [&](int buf, int ch) {
        int k0 = ch * PKCH;
#pragma unroll
        for (int r = 0; r < 4; r++) {
            int idx = r * 256 + tid;          // 0..1023
            int row = idx >> 3, col = (idx & 7) * 8;
            uint32_t off = SW128((uint32_t)(row * 128 + col * 2));
            cp_async16(sm + PSM_A_HI(buf) + off, Ahi + (size_t)row * KDIM + k0 + col);
            cp_async16(sm + PSM_A_LO(buf) + off, Alo + (size_t)row * KDIM + k0 + col);
        }
#pragma unroll
        for (int r = 0; r < 2; r++) {
            int idx = r * 256 + tid;          // 0..511
            int row = idx >> 3, col = (idx & 7) * 8;
            uint32_t off = SW128((uint32_t)(row * 128 + col * 2));
            cp_async16(sm + PSM_B_HI(buf) + off, Bhi + (size_t)row * KDIM + k0 + col);
            cp_async16(sm + PSM_B_LO(buf) + off, Blo + (size_t)row * KDIM + k0 + col);
        }
        CP_COMMIT();
    };

    float acc[4][2][4];
#pragma unroll
    for (int mt = 0; mt < 4; mt++)
#pragma unroll
        for (int nt = 0; nt < 2; nt++)
#pragma unroll
            for (int r = 0; r < 4; r++) acc[mt][nt][r] = 0.0f;

    int wr = wid >> 2;      // 0..1
    int wc = wid & 3;       // 0..3
    int lt = lid >> 3, lr = lid & 7;

    fill(0, 0);
    for (int ch = 0; ch < 4; ch++) {
        int buf = ch & 1;
        if (ch < 3) fill(buf ^ 1, ch + 1);
        if (ch < 3) CP_WAIT1(); else CP_WAIT0();
        __syncthreads();

#pragma unroll
        for (int ks = 0; ks < 4; ks++) {
            int k0 = ks * 16;
            uint32_t Ah[4][4], Al[4][4];
#pragma unroll
            for (int mt = 0; mt < 4; mt++) {
                uint32_t off = SW128((uint32_t)(
                    (wr * 64 + mt * 16 + (lt & 1) * 8 + lr) * 128 +
                    (k0 + (lt >> 1) * 8) * 2));
                ldsm_x4(Ah[mt], sm + PSM_A_HI(buf) + off);
                ldsm_x4(Al[mt], sm + PSM_A_LO(buf) + off);
            }
            uint32_t Bh[2][2], Bl[2][2];
#pragma unroll
            for (int nt = 0; nt < 2; nt++) {
                uint32_t off = SW128((uint32_t)(
                    (wc * 16 + nt * 8 + lr) * 128 + (k0 + (lt & 1) * 8) * 2));
                ldsm_x2(Bh[nt], sm + PSM_B_HI(buf) + off);
                ldsm_x2(Bl[nt], sm + PSM_B_LO(buf) + off);
            }
#pragma unroll
            for (int mt = 0; mt < 4; mt++)
#pragma unroll
                for (int nt = 0; nt < 2; nt++) {
                    mma_bf16(acc[mt][nt], Ah[mt], Bh[nt][0], Bh[nt][1]);
                    mma_bf16(acc[mt][nt], Ah[mt], Bl[nt][0], Bl[nt][1]);
                    mma_bf16(acc[mt][nt], Al[mt], Bh[nt][0], Bh[nt][1]);
                }
        }
        __syncthreads();
    }

    int Rb = wr * 64 + (lid >> 2);
    int Cb = wc * 16 + (lid & 3) * 2;
#pragma unroll
    for (int mt = 0; mt < 4; mt++)
#pragma unroll
        for (int h = 0; h < 2; h++) {
            size_t row = (size_t)(row0 + Rb + mt * 16 + h * 8) * KDIM;
#pragma unroll
            for (int nt = 0; nt < 2; nt++) {
                size_t o = row + n0 + Cb + nt * 8;
                float c0 = acc[mt][nt][h * 2 + 0];
                float c1 = acc[mt][nt][h * 2 + 1];
                __nv_bfloat16 h0 = __float2bfloat16(c0);
                __nv_bfloat16 h1 = __float2bfloat16(c1);
                __nv_bfloat16 l0 = __float2bfloat16(c0 - __bfloat162float(h0));
                __nv_bfloat16 l1 = __float2bfloat16(c1 - __bfloat162float(h1));
                *(__nv_bfloat162*)(Chi + o) = __nv_bfloat162(h0, h1);
                *(__nv_bfloat162*)(Clo + o) = __nv_bfloat162(l0, l1);
            }
        }
}

// ---------------------------------------------------------------------------
// Score GEMM (3-term bf16 mma.sync) + fused epilogue.
// CTA 64(n) x 128(m), 128 threads (4 warps), warp tile 64x32.
// KCH=32, SW64 rows (64B). SMEM 2 bufs x 24KB = 48KB -> 3 CTAs/SM.
// ---------------------------------------------------------------------------
#define SKCH 32
#define SSM_BUF(b)  ((b) * 24576)
#define SSM_A_HI(b) (SSM_BUF(b) + 0)
#define SSM_A_LO(b) (SSM_BUF(b) + 4096)
#define SSM_B_HI(b) (SSM_BUF(b) + 8192)
#define SSM_B_LO(b) (SSM_BUF(b) + 16384)
#define SSM_TOTAL   (2 * 24576)

__global__ __launch_bounds__(128, 3) void score_kernel(
    const float* __restrict__ adj,
    float* __restrict__ out)
{
    extern __shared__ __align__(1024) char smem[];
    uint32_t sm = smem_u32(smem);
    int tid = threadIdx.x;
    int wid = tid >> 5, lid = tid & 31;
    int b = blockIdx.z;
    int n0 = blockIdx.x * 64;      // output rows
    int m0 = blockIdx.y * 128;     // output cols

    const size_t boff = (size_t)b * NN * KDIM;
    const __nv_bfloat16* Ahi = g_c1hi + boff + (size_t)n0 * KDIM;
    const __nv_bfloat16* Alo = g_c1lo + boff + (size_t)n0 * KDIM;
    const __nv_bfloat16* Bhi = g_c2hi + boff + (size_t)m0 * KDIM;
    const __nv_bfloat16* Blo = g_c2lo + boff + (size_t)m0 * KDIM;

    auto fill = [&](int buf, int ch) {
        int k0 = ch * SKCH;
        // A tiles: 64 rows x 32 bf16 (64B rows) -> 256 granules -> 2/thread.
#pragma unroll
        for (int r = 0; r < 2; r++) {
            int idx = r * 128 + tid;          // 0..255
            int row = idx >> 2, col = (idx & 3) * 8;
            uint32_t off = SW64((uint32_t)(row * 64 + col * 2));
            cp_async16(sm + SSM_A_HI(buf) + off, Ahi + (size_t)row * KDIM + k0 + col);
            cp_async16(sm + SSM_A_LO(buf) + off, Alo + (size_t)row * KDIM + k0 + col);
        }
        // B tiles: 128 rows x 32 bf16 -> 512 granules -> 4/thread.
#pragma unroll
        for (int r = 0; r < 4; r++) {
            int idx = r * 128 + tid;          // 0..511
            int row = idx >> 2, col = (idx & 3) * 8;
            uint32_t off = SW64((uint32_t)(row * 64 + col * 2));
            cp_async16(sm + SSM_B_HI(buf) + off, Bhi + (size_t)row * KDIM + k0 + col);
            cp_async16(sm + SSM_B_LO(buf) + off, Blo + (size_t)row * KDIM + k0 + col);
        }
        CP_COMMIT();
    };

    float acc[4][4][4];
#pragma unroll
    for (int mt = 0; mt < 4; mt++)
#pragma unroll
        for (int nt = 0; nt < 4; nt++)
#pragma unroll
            for (int r = 0; r < 4; r++) acc[mt][nt][r] = 0.0f;

    int wc = wid;           // 0..3 : 32-col block
    int lt = lid >> 3, lr = lid & 7;

    fill(0, 0);
    for (int ch = 0; ch < 8; ch++) {
        int buf = ch & 1;
        if (ch < 7) fill(buf ^ 1, ch + 1);
        if (ch < 7) CP_WAIT1(); else CP_WAIT0();
        __syncthreads();

#pragma unroll
        for (int ks = 0; ks < 2; ks++) {
            int k0 = ks * 16;
            uint32_t Ah[4][4], Al[4][4];
#pragma unroll
            for (int mt = 0; mt < 4; mt++) {
                uint32_t off = SW64((uint32_t)(
                    (mt * 16 + (lt & 1) * 8 + lr) * 64 +
                    (k0 + (lt >> 1) * 8) * 2));
                ldsm_x4(Ah[mt], sm + SSM_A_HI(buf) + off);
                ldsm_x4(Al[mt], sm + SSM_A_LO(buf) + off);
            }
            uint32_t Bh[4][2], Bl[4][2];
#pragma unroll
            for (int nt = 0; nt < 4; nt++) {
                uint32_t off = SW64((uint32_t)(
                    (wc * 32 + nt * 8 + lr) * 64 + (k0 + (lt & 1) * 8) * 2));
                ldsm_x2(Bh[nt], sm + SSM_B_HI(buf) + off);
                ldsm_x2(Bl[nt], sm + SSM_B_LO(buf) + off);
            }
#pragma unroll
            for (int mt = 0; mt < 4; mt++)
#pragma unroll
                for (int nt = 0; nt < 4; nt++) {
                    mma_bf16(acc[mt][nt], Ah[mt], Bh[nt][0], Bh[nt][1]);
                    mma_bf16(acc[mt][nt], Ah[mt], Bl[nt][0], Bl[nt][1]);
                    mma_bf16(acc[mt][nt], Al[mt], Bh[nt][0], Bh[nt][1]);
                }
        }
        __syncthreads();
    }

    // Fused epilogue straight from accumulators.
    const float* adj_b = adj + ((size_t)b * NN + n0) * NN + m0;
    float* out_b = out + ((size_t)b * NN + n0) * NN + m0;
    int Rb = lid >> 2;
    int Cb = wc * 32 + (lid & 3) * 2;
#pragma unroll
    for (int mt = 0; mt < 4; mt++) {
#pragma unroll
        for (int h = 0; h < 2; h++) {
            size_t row = (size_t)(Rb + mt * 16 + h * 8) * NN;
#pragma unroll
            for (int nt = 0; nt < 4; nt++) {
                size_t o = row + Cb + nt * 8;
                float2 a2 = *(const float2*)(adj_b + o);
                float2 r;
                r.x = epi(acc[mt][nt][h * 2 + 0], a2.x);
                r.y = epi(acc[mt][nt][h * 2 + 1], a2.y);
                *(float2*)(out_b + o) = r;
            }
        }
    }
}

extern "C" void kernel_launch(void* const* d_in, const int* in_sizes, int n_in,
                              void* d_out, int out_size) {
    const float* v   = (const float*)d_in[0];
    const float* adj = (const float*)d_in[1];
    const float* W1  = (const float*)d_in[2];
    const float* W2  = (const float*)d_in[3];
    float* out = (float*)d_out;

    const long adj_elems = 8L * 2048 * 2048;
    long off = (long)out_size - adj_elems;
    if (off < 0) off = 0;
    float* norm_adj = out + off;
    float* out_v = (off > 0) ? out : nullptr;

    // 1. Split v/W into bf16 hi/lo (+ v passthrough copy).
    int split_ctas = (NV / 4 + 2 * (NW / 4) + 255) / 256;
    split_kernel<<<split_ctas, 256>>>(v, W1, W2, out_v);

    // 2. Projections via mma.sync -> g_c{1,2}{hi,lo}.
    cudaFuncSetAttribute(proj_kernel,
                         cudaFuncAttributeMaxDynamicSharedMemorySize, PSM_TOTAL);
    dim3 pgrid(16384 / 128, 256 / 64, 2);
    proj_kernel<<<pgrid, 256, PSM_TOTAL>>>();

    // 3. Score GEMM + fused epilogue (3 CTAs/SM).
    cudaFuncSetAttribute(score_kernel,
                         cudaFuncAttributeMaxDynamicSharedMemorySize, SSM_TOTAL);
    dim3 sgrid(NN / 64, NN / 128, BATCH);
    score_kernel<<<sgrid, 128, SSM_TOTAL>>>(adj, norm_adj);
}